// round 14
// baseline (speedup 1.0000x reference)
#include <cuda_runtime.h>
#include <math.h>

#define BB   256
#define HH   32
#define WW   32
#define AA   5
#define NCC  20
#define MM   50
#define NOBJ (BB*MM)

#define GRID    1280                   // 128-thr blocks; 5 blocks per batch
#define NTHR    128
#define NF4     (BB*AA*256)            // 327680 conf float4s = GRID*NTHR*2
#define HALF    (GRID*NTHR)            // 163840
#define OPB     10                     // 1280*10 = 12800; one batch per block

// Zero-init at load; last block resets accumulators each launch -> replay-safe.
__device__ float    g_acc[4];
__device__ unsigned g_cnt;

// sigmoid via single-MUFU tanh.approx: sigma(x) = 0.5*tanh(x/2) + 0.5
__device__ __forceinline__ float sigm(float x) {
    float t;
    asm("tanh.approx.f32 %0, %1;" : "=f"(t) : "f"(x * 0.5f));
    return fmaf(0.5f, t, 0.5f);
}

__device__ __forceinline__ const float4* conf_ptr(const float4* out4, int t) {
    int b = t / (AA * 256);
    int r = t - b * (AA * 256);
    int a = r >> 8;
    int q = r & 255;
    return out4 + (size_t)(b * 125 + a * 25 + NCC) * 256 + q;
}

__global__ void __launch_bounds__(128, 10)
fused_loss_kernel(const float* __restrict__ out,
                  const float4* __restrict__ gt_boxes,
                  const float* __restrict__ anchor,
                  const int* __restrict__ gt_classes,
                  const int* __restrict__ num_box,
                  float* __restrict__ dout) {
    __shared__ int    s_cell[MM];       // this block's single batch
    __shared__ int    s_cls [MM];
    __shared__ float4 s_gt  [MM];
    __shared__ int    s_meta[OPB];      // packed cell | cls<<10
    __shared__ float4 s_box [OPB];      // tx,ty,tw,th (already *32)
    __shared__ int    s_nrec;
    __shared__ float  s_part[4];        // box, conf, noobj-corr, cls (sparse)
    __shared__ float  sm[4];            // per-warp noobj partials

    int tid  = threadIdx.x;
    int lane = tid & 31;
    int wid  = tid >> 5;
    float noobj = 0.0f;

    int bb    = blockIdx.x / 5;         // batch of this block
    int mbase = (blockIdx.x % 5) * OPB; // object sub-range within the batch

    // ---- issue dense loads + phase-0 gt loads; all overlap ----
    int gid = blockIdx.x * NTHR + tid;
    const float4* out4 = (const float4*)out;
    float4 v0 = *conf_ptr(out4, gid);
    float4 v1 = *conf_ptr(out4, gid + HALF);

    if (tid == 0) s_nrec = 0;
    if (tid < 4) s_part[tid] = 0.0f;
    int nb = num_box[bb]; if (nb > MM) nb = MM;
    float4 gtb; int clv = 0;
    if (tid < MM) {
        gtb = gt_boxes[bb * MM + tid];
        clv = gt_classes[bb * MM + tid];
    }

    // ---- consume dense loads while the gt LDGs are still in flight ----
    {
        float s, n2 = 0.0f;
        s = sigm(v0.x); noobj = fmaf(s, s, noobj);
        s = sigm(v0.y); n2    = fmaf(s, s, n2);
        s = sigm(v0.z); noobj = fmaf(s, s, noobj);
        s = sigm(v0.w); n2    = fmaf(s, s, n2);
        s = sigm(v1.x); noobj = fmaf(s, s, noobj);
        s = sigm(v1.y); n2    = fmaf(s, s, n2);
        s = sigm(v1.z); noobj = fmaf(s, s, noobj);
        s = sigm(v1.w); n2    = fmaf(s, s, n2);
        noobj += n2;
    }

    // ---- phase 0: store cells/classes/boxes of the batch to smem ----
    if (tid < MM) {
        int cellv = -1;
        if (tid < nb) {
            int gx = (int)(gtb.x * 32.0f);
            int gy = (int)(gtb.y * 32.0f);
            cellv = gy * WW + gx;
        }
        s_cell[tid] = cellv;
        s_cls [tid] = clv;
        s_gt  [tid] = gtb;
    }
    __syncthreads();

    // ---- phase 1: winner check for this block's 10 objects + compaction ----
    if (tid < OPB) {
        int m = mbase + tid;
        int mycell = (m < MM) ? s_cell[m] : -1;
        if (mycell >= 0) {
            int last = -1, minc = 1 << 30;
            #pragma unroll
            for (int m2 = 0; m2 < MM; m2++) {
                int c2 = s_cell[m2];
                if (c2 == mycell) {
                    last = m2;
                    int cc = s_cls[m2];
                    minc = (cc < minc) ? cc : minc;
                }
            }
            if (last == m) {
                int r = atomicAdd(&s_nrec, 1);
                s_meta[r] = mycell | (minc << 10);
                float4 bx = s_gt[m];
                s_box[r] = make_float4(bx.x * 32.0f, bx.y * 32.0f,
                                       bx.z * 32.0f, bx.w * 32.0f);
            }
        }
    }
    __syncthreads();

    // ---- phase 2: warp-cooperative winner processing (reduced-SHFL form) ----
    {
        const unsigned FULL = 0xffffffffu;
        int a_id = lane / 5, ch = lane - a_id * 5;
        float anc = 1.0f;
        if (lane < 25 && ch >= 3) anc = anchor[2 * a_id + (ch - 3)];
        int nrec = s_nrec;
        const float* batb = out + (size_t)bb * 128000;
        for (int r = wid; r < nrec; r += 4) {
            int   meta = s_meta[r];
            float4 tb  = s_box[r];
            int cell = meta & 1023;
            int cls  = meta >> 10;
            const float* cellb = batb + cell;
            int wq = cell & 31, hq = (cell >> 5) & 31;

            // one LDG: 25 anchor-stat values in flight at once
            float v = 0.0f;
            if (lane < 25) v = cellb[(a_id * 25 + NCC + ch) * 1024];
            float tval = (ch <= 2) ? sigm(v) : __expf(v) * anc;
            float s1 = __shfl_sync(FULL, tval, lane + 1);
            float s2 = __shfl_sync(FULL, tval, lane + 2);
            float s3 = __shfl_sync(FULL, tval, lane + 3);
            float s4 = __shfl_sync(FULL, tval, lane + 4);

            float tx = tb.x, ty = tb.y, tw = tb.z, th = tb.w;
            float tx1 = tx - tw * 0.5f, ty1 = ty - th * 0.5f;
            float tx2 = tx + tw * 0.5f, ty2 = ty + th * 0.5f;
            float tarea = tw * th;

            float iou = -2.0f;
            if (lane < 25 && ch == 0) {               // anchor-lead lanes
                float px = (float)wq + s1, py = (float)hq + s2;
                float pw = s3, ph = s4;
                float ax1 = px - pw * 0.5f, ay1 = py - ph * 0.5f;
                float ax2 = px + pw * 0.5f, ay2 = py + ph * 0.5f;
                float iw = fmaxf(fminf(ax2, tx2) - fmaxf(ax1, tx1), 0.0f);
                float ih = fmaxf(fminf(ay2, ty2) - fmaxf(ay1, ty1), 0.0f);
                float inter = iw * ih;
                float uni = pw * ph + tarea - inter;
                iou = inter / fmaxf(uni, 1e-10f);
            }
            // gather 5 ious to all lanes (5 SHFL), scalar argmax (first max wins)
            float i0 = __shfl_sync(FULL, iou, 0);
            float i1 = __shfl_sync(FULL, iou, 5);
            float i2 = __shfl_sync(FULL, iou, 10);
            float i3 = __shfl_sync(FULL, iou, 15);
            float i4 = __shfl_sync(FULL, iou, 20);
            int best = 0; float bi = i0;
            if (i1 > bi) { bi = i1; best = 1; }
            if (i2 > bi) { bi = i2; best = 2; }
            if (i3 > bi) { bi = i3; best = 3; }
            if (i4 > bi) { bi = i4; best = 4; }
            // fetch best anchor's 5 values by lane index (5 SHFL)
            int bl = best * 5;
            float pcb = __shfl_sync(FULL, tval, bl);
            float bxo = __shfl_sync(FULL, tval, bl + 1);
            float byo = __shfl_sync(FULL, tval, bl + 2);
            float bw  = __shfl_sync(FULL, tval, bl + 3);
            float bh  = __shfl_sync(FULL, tval, bl + 4);

            // one LDG: the best anchor's 20 class logits; shfl softmax
            float lv = (lane < NCC) ? cellb[(best * 25 + lane) * 1024] : -1e30f;
            float mx = lv;
            #pragma unroll
            for (int o = 16; o > 0; o >>= 1)
                mx = fmaxf(mx, __shfl_xor_sync(FULL, mx, o));
            float ex = (lane < NCC) ? __expf(lv - mx) : 0.0f;
            #pragma unroll
            for (int o = 16; o > 0; o >>= 1)
                ex += __shfl_xor_sync(FULL, ex, o);
            float lc = __shfl_sync(FULL, lv, cls);

            if (lane == 0) {
                float d0 = ((float)wq + bxo) - tx;
                float d1 = ((float)hq + byo) - ty;
                float d2 = sqrtf(bw) - sqrtf(tw);
                float d3 = sqrtf(bh) - sqrtf(th);
                atomicAdd(&s_part[0], d0*d0 + d1*d1 + d2*d2 + d3*d3);
                atomicAdd(&s_part[1], (pcb - 1.0f) * (pcb - 1.0f));
                atomicAdd(&s_part[2], -pcb * pcb);   // remove best from noobj
                atomicAdd(&s_part[3], mx + __logf(ex) - lc);
            }
        }
    }

    // ---- block reduction: noobj only via shuffles ----
    #pragma unroll
    for (int off = 16; off > 0; off >>= 1)
        noobj += __shfl_down_sync(0xffffffffu, noobj, off);
    if (lane == 0) sm[wid] = noobj;
    __syncthreads();
    if (tid == 0) {
        float s2 = sm[0] + sm[1] + sm[2] + sm[3] + s_part[2];
        float s0 = s_part[0], s1 = s_part[1], s3 = s_part[3];
        if (s0 != 0.0f) atomicAdd(&g_acc[0], s0);
        if (s1 != 0.0f) atomicAdd(&g_acc[1], s1);
        atomicAdd(&g_acc[2], s2);
        if (s3 != 0.0f) atomicAdd(&g_acc[3], s3);
        __threadfence();
        unsigned old = atomicInc(&g_cnt, GRID - 1);
        if (old == GRID - 1) {                  // last block finalizes
            volatile float* a = g_acc;
            dout[0] = a[0] * (5.0f / 256.0f);   // LAM_COORD / B
            dout[1] = a[1] * (1.0f / 256.0f);   // LAM_OBJ   / B
            dout[2] = a[2] * (0.5f / 256.0f);   // LAM_NOOBJ / B
            dout[3] = a[3] * (1.0f / 256.0f);   // LAM_CLS   / B
            g_acc[0] = 0.0f; g_acc[1] = 0.0f;   // reset for next replay
            g_acc[2] = 0.0f; g_acc[3] = 0.0f;
        }
    }
}

extern "C" void kernel_launch(void* const* d_in, const int* in_sizes, int n_in,
                              void* d_out, int out_size) {
    const float*  out_t      = (const float*)d_in[0];
    const float4* gt_boxes   = (const float4*)d_in[1];
    const float*  anchor     = (const float*)d_in[2];
    const int*    gt_classes = (const int*)d_in[3];
    const int*    num_box    = (const int*)d_in[4];
    float* dout = (float*)d_out;

    fused_loss_kernel<<<GRID, NTHR>>>(out_t, gt_boxes, anchor,
                                      gt_classes, num_box, dout);
}

// round 15
// speedup vs baseline: 1.0172x; 1.0172x over previous
#include <cuda_runtime.h>
#include <math.h>

#define BB   256
#define HH   32
#define WW   32
#define AA   5
#define NCC  20
#define MM   50
#define NOBJ (BB*MM)

#define GRID    1280                   // 128-thr blocks; 5 blocks per batch
#define NTHR    128
#define NF4     (BB*AA*256)            // 327680 conf float4s = GRID*NTHR*2
#define HALF    (GRID*NTHR)            // 163840
#define OPB     10                     // 1280*10 = 12800; one batch per block
#define NCELL   (HH*WW)

// Zero-init at load; last block resets accumulators each launch -> replay-safe.
__device__ float    g_acc[4];
__device__ unsigned g_cnt;

// sigmoid via single-MUFU tanh.approx: sigma(x) = 0.5*tanh(x/2) + 0.5
__device__ __forceinline__ float sigm(float x) {
    float t;
    asm("tanh.approx.f32 %0, %1;" : "=f"(t) : "f"(x * 0.5f));
    return fmaf(0.5f, t, 0.5f);
}

__device__ __forceinline__ const float4* conf_ptr(const float4* out4, int t) {
    int b = t / (AA * 256);
    int r = t - b * (AA * 256);
    int a = r >> 8;
    int q = r & 255;
    return out4 + (size_t)(b * 125 + a * 25 + NCC) * 256 + q;
}

__global__ void __launch_bounds__(128, 10)
fused_loss_kernel(const float* __restrict__ out,
                  const float4* __restrict__ gt_boxes,
                  const float* __restrict__ anchor,
                  const int* __restrict__ gt_classes,
                  const int* __restrict__ num_box,
                  float* __restrict__ dout) {
    __shared__ int    s_win[NCELL];     // winner scatter table: max(m+1)
    __shared__ int    s_clw[NCELL];     // min class per cell
    __shared__ int    s_cell[MM];       // cell of each object (or -1)
    __shared__ float4 s_gt  [MM];
    __shared__ int    s_meta[OPB];      // packed cell | cls<<10
    __shared__ float4 s_box [OPB];      // tx,ty,tw,th (already *32)
    __shared__ int    s_nrec;
    __shared__ float  sm[4][4];

    int tid  = threadIdx.x;
    int lane = tid & 31;
    int wid  = tid >> 5;
    float boxl = 0.0f, confl = 0.0f, noobj = 0.0f, clsl = 0.0f;

    int bb    = blockIdx.x / 5;         // batch of this block
    int mbase = (blockIdx.x % 5) * OPB; // object sub-range within the batch

    // ---- issue dense loads + gt loads; zero tables while they fly ----
    int gid = blockIdx.x * NTHR + tid;
    const float4* out4 = (const float4*)out;
    float4 v0 = *conf_ptr(out4, gid);
    float4 v1 = *conf_ptr(out4, gid + HALF);

    if (tid == 0) s_nrec = 0;
    int nb = num_box[bb]; if (nb > MM) nb = MM;
    float4 gtb; int clv = 0;
    if (tid < MM) {
        gtb = gt_boxes[bb * MM + tid];
        clv = gt_classes[bb * MM + tid];
    }

    // zero the scatter tables (8 int4 stores per thread)
    {
        int4 z0 = make_int4(0, 0, 0, 0);
        int4 zM = make_int4(0x7fffffff, 0x7fffffff, 0x7fffffff, 0x7fffffff);
        #pragma unroll
        for (int k = 0; k < 2; k++) {
            ((int4*)s_win)[tid + k * NTHR] = z0;
            ((int4*)s_clw)[tid + k * NTHR] = zM;
        }
    }

    // ---- consume dense loads while the gt LDGs are still in flight ----
    {
        float s, n2 = 0.0f;
        s = sigm(v0.x); noobj = fmaf(s, s, noobj);
        s = sigm(v0.y); n2    = fmaf(s, s, n2);
        s = sigm(v0.z); noobj = fmaf(s, s, noobj);
        s = sigm(v0.w); n2    = fmaf(s, s, n2);
        s = sigm(v1.x); noobj = fmaf(s, s, noobj);
        s = sigm(v1.y); n2    = fmaf(s, s, n2);
        s = sigm(v1.z); noobj = fmaf(s, s, noobj);
        s = sigm(v1.w); n2    = fmaf(s, s, n2);
        noobj += n2;
    }

    // ---- phase 0: compute cells; store gt to smem ----
    int mycellw = -1;
    if (tid < MM) {
        if (tid < nb) {
            int gx = (int)(gtb.x * 32.0f);
            int gy = (int)(gtb.y * 32.0f);
            mycellw = gy * WW + gx;
        }
        s_cell[tid] = mycellw;
        s_gt  [tid] = gtb;
    }
    __syncthreads();

    // ---- phase 1a: scatter reductions (last-m wins, min class) ----
    if (tid < MM && mycellw >= 0) {
        atomicMax(&s_win[mycellw], tid + 1);
        atomicMin(&s_clw[mycellw], clv);
    }
    __syncthreads();

    // ---- phase 1b: winner check for this block's 10 objects + compaction ----
    if (tid < OPB) {
        int m = mbase + tid;
        int mycell = s_cell[m];
        if (mycell >= 0 && s_win[mycell] == m + 1) {
            int r = atomicAdd(&s_nrec, 1);
            s_meta[r] = mycell | (s_clw[mycell] << 10);
            float4 bx = s_gt[m];
            s_box[r] = make_float4(bx.x * 32.0f, bx.y * 32.0f,
                                   bx.z * 32.0f, bx.w * 32.0f);
        }
    }
    __syncthreads();

    // ---- phase 2: warp-cooperative winner processing (4 warps round-robin) ----
    {
        const unsigned FULL = 0xffffffffu;
        int a_id = lane / 5, ch = lane - a_id * 5;
        float anc = 1.0f;
        if (lane < 25 && ch >= 3) anc = anchor[2 * a_id + (ch - 3)];
        int nrec = s_nrec;
        const float* batb = out + (size_t)bb * 128000;
        for (int r = wid; r < nrec; r += 4) {
            int   meta = s_meta[r];
            float4 tb  = s_box[r];
            int cell = meta & 1023;
            int cls  = meta >> 10;
            const float* cellb = batb + cell;
            int wq = cell & 31, hq = (cell >> 5) & 31;

            // one LDG: 25 anchor-stat values in flight at once
            float v = 0.0f;
            if (lane < 25) v = cellb[(a_id * 25 + NCC + ch) * 1024];
            float tval = (ch <= 2) ? sigm(v) : __expf(v) * anc;
            float s1 = __shfl_sync(FULL, tval, lane + 1);
            float s2 = __shfl_sync(FULL, tval, lane + 2);
            float s3 = __shfl_sync(FULL, tval, lane + 3);
            float s4 = __shfl_sync(FULL, tval, lane + 4);

            float tx = tb.x, ty = tb.y, tw = tb.z, th = tb.w;
            float tx1 = tx - tw * 0.5f, ty1 = ty - th * 0.5f;
            float tx2 = tx + tw * 0.5f, ty2 = ty + th * 0.5f;
            float tarea = tw * th;

            float iou = -2.0f;
            if (lane < 25 && ch == 0) {               // anchor-lead lanes
                float px = (float)wq + s1, py = (float)hq + s2;
                float pw = s3, ph = s4;
                float ax1 = px - pw * 0.5f, ay1 = py - ph * 0.5f;
                float ax2 = px + pw * 0.5f, ay2 = py + ph * 0.5f;
                float iw = fmaxf(fminf(ax2, tx2) - fmaxf(ax1, tx1), 0.0f);
                float ih = fmaxf(fminf(ay2, ty2) - fmaxf(ay1, ty1), 0.0f);
                float inter = iw * ih;
                float uni = pw * ph + tarea - inter;
                iou = inter / fmaxf(uni, 1e-10f);
            }
            // gather 5 ious (5 SHFL), scalar argmax (first max wins)
            float i0 = __shfl_sync(FULL, iou, 0);
            float i1 = __shfl_sync(FULL, iou, 5);
            float i2 = __shfl_sync(FULL, iou, 10);
            float i3 = __shfl_sync(FULL, iou, 15);
            float i4 = __shfl_sync(FULL, iou, 20);
            int best = 0; float bi = i0;
            if (i1 > bi) { bi = i1; best = 1; }
            if (i2 > bi) { bi = i2; best = 2; }
            if (i3 > bi) { bi = i3; best = 3; }
            if (i4 > bi) { bi = i4; best = 4; }
            int bl = best * 5;
            float pcb = __shfl_sync(FULL, tval, bl);
            float bxo = __shfl_sync(FULL, tval, bl + 1);
            float byo = __shfl_sync(FULL, tval, bl + 2);
            float bw  = __shfl_sync(FULL, tval, bl + 3);
            float bh  = __shfl_sync(FULL, tval, bl + 4);

            // one LDG: the best anchor's 20 class logits; shfl softmax
            float lv = (lane < NCC) ? cellb[(best * 25 + lane) * 1024] : -1e30f;
            float mx = lv;
            #pragma unroll
            for (int o = 16; o > 0; o >>= 1)
                mx = fmaxf(mx, __shfl_xor_sync(FULL, mx, o));
            float ex = (lane < NCC) ? __expf(lv - mx) : 0.0f;
            #pragma unroll
            for (int o = 16; o > 0; o >>= 1)
                ex += __shfl_xor_sync(FULL, ex, o);
            float lc = __shfl_sync(FULL, lv, cls);

            if (lane == 0) {
                float d0 = ((float)wq + bxo) - tx;
                float d1 = ((float)hq + byo) - ty;
                float d2 = sqrtf(bw) - sqrtf(tw);
                float d3 = sqrtf(bh) - sqrtf(th);
                boxl  += d0 * d0 + d1 * d1 + d2 * d2 + d3 * d3;
                confl += (pcb - 1.0f) * (pcb - 1.0f);
                noobj -= pcb * pcb;                    // remove best from noobj
                clsl  += mx + __logf(ex) - lc;
            }
        }
    }

    // ---- block reduction (4 warps) ----
    #pragma unroll
    for (int off = 16; off > 0; off >>= 1) {
        boxl  += __shfl_down_sync(0xffffffffu, boxl,  off);
        confl += __shfl_down_sync(0xffffffffu, confl, off);
        noobj += __shfl_down_sync(0xffffffffu, noobj, off);
        clsl  += __shfl_down_sync(0xffffffffu, clsl,  off);
    }
    if (lane == 0) {
        sm[0][wid] = boxl; sm[1][wid] = confl;
        sm[2][wid] = noobj; sm[3][wid] = clsl;
    }
    __syncthreads();
    if (tid == 0) {
        float s0 = 0, s1 = 0, s2 = 0, s3 = 0;
        #pragma unroll
        for (int k = 0; k < 4; k++) {
            s0 += sm[0][k]; s1 += sm[1][k]; s2 += sm[2][k]; s3 += sm[3][k];
        }
        if (s0 != 0.0f) atomicAdd(&g_acc[0], s0);
        if (s1 != 0.0f) atomicAdd(&g_acc[1], s1);
        atomicAdd(&g_acc[2], s2);
        if (s3 != 0.0f) atomicAdd(&g_acc[3], s3);
        __threadfence();
        unsigned old = atomicInc(&g_cnt, GRID - 1);
        if (old == GRID - 1) {                  // last block finalizes
            volatile float* a = g_acc;
            dout[0] = a[0] * (5.0f / 256.0f);   // LAM_COORD / B
            dout[1] = a[1] * (1.0f / 256.0f);   // LAM_OBJ   / B
            dout[2] = a[2] * (0.5f / 256.0f);   // LAM_NOOBJ / B
            dout[3] = a[3] * (1.0f / 256.0f);   // LAM_CLS   / B
            g_acc[0] = 0.0f; g_acc[1] = 0.0f;   // reset for next replay
            g_acc[2] = 0.0f; g_acc[3] = 0.0f;
        }
    }
}

extern "C" void kernel_launch(void* const* d_in, const int* in_sizes, int n_in,
                              void* d_out, int out_size) {
    const float*  out_t      = (const float*)d_in[0];
    const float4* gt_boxes   = (const float4*)d_in[1];
    const float*  anchor     = (const float*)d_in[2];
    const int*    gt_classes = (const int*)d_in[3];
    const int*    num_box    = (const int*)d_in[4];
    float* dout = (float*)d_out;

    fused_loss_kernel<<<GRID, NTHR>>>(out_t, gt_boxes, anchor,
                                      gt_classes, num_box, dout);
}